// round 1
// baseline (speedup 1.0000x reference)
#include <cuda_runtime.h>

#define NQ       12
#define DIM      4096          // 2^12 amplitudes
#define NPAIRS   (DIM / 2)
#define THREADS  256
#define NCLASSES 10
#define NFEAT    (3 * NQ)      // 36

struct Cx { float x, y; };

__device__ __forceinline__ Cx cmul(Cx a, Cx b) {
    return Cx{a.x * b.x - a.y * b.y, a.x * b.y + a.y * b.x};
}

__global__ __launch_bounds__(THREADS)
void qsim_kernel(const float* __restrict__ sv,
                 const float* __restrict__ angles,
                 const float* __restrict__ Wm,
                 const float* __restrict__ bv,
                 float* __restrict__ out)
{
    __shared__ float re[DIM];
    __shared__ float im[DIM];
    __shared__ float2 Ufused[24][4];   // [layer*12+wire][00,01,10,11]
    __shared__ float crx_c[24], crx_s[24];
    __shared__ float feats[NFEAT];

    const int tid  = threadIdx.x;
    const int bidx = blockIdx.x;

    // ---- Precompute fused 1q matrices (RZ*RY*RX per wire per layer) + CRX angles ----
    if (tid < 24) {
        const int layer = tid / NQ;
        const int wire  = tid % NQ;
        const int base  = layer * 48;
        const float tx = angles[base + wire];
        const float ty = angles[base + 12 + wire];
        const float tz = angles[base + 24 + wire];
        const float cx = cosf(0.5f * tx), sx = sinf(0.5f * tx);
        const float cy = cosf(0.5f * ty), sy = sinf(0.5f * ty);
        const float cz = cosf(0.5f * tz), sz = sinf(0.5f * tz);
        // M = Ry * Rx   (Rx = [[c,-is],[-is,c]], Ry = [[c,-s],[s,c]])
        Cx m00{cy * cx,  sy * sx};
        Cx m01{-sy * cx, -cy * sx};
        Cx m10{sy * cx,  -cy * sx};
        Cx m11{cy * cx,  -sy * sx};
        // U = Rz * M    (Rz = diag(e^{-i tz/2}, e^{+i tz/2}))
        Cx ezm{cz, -sz}, ezp{cz, sz};
        Cx u00 = cmul(ezm, m00), u01 = cmul(ezm, m01);
        Cx u10 = cmul(ezp, m10), u11 = cmul(ezp, m11);
        Ufused[tid][0] = make_float2(u00.x, u00.y);
        Ufused[tid][1] = make_float2(u01.x, u01.y);
        Ufused[tid][2] = make_float2(u10.x, u10.y);
        Ufused[tid][3] = make_float2(u11.x, u11.y);
        // CRX angle in tape order: slot k of layer -> angles[48*layer + 36 + k]
        const float tc = angles[base + 36 + wire];
        crx_c[tid] = cosf(0.5f * tc);
        crx_s[tid] = sinf(0.5f * tc);
    }
    if (tid < NFEAT) feats[tid] = 0.0f;

    // ---- Load state (real input, imag = 0) ----
    const float* in = sv + (size_t)bidx * DIM;
    #pragma unroll
    for (int i = tid; i < DIM; i += THREADS) {
        re[i] = in[i];
        im[i] = 0.0f;
    }
    __syncthreads();

    // ---- Apply 2 layers ----
    for (int layer = 0; layer < 2; ++layer) {
        // 12 fused single-qubit gates
        for (int wire = 0; wire < NQ; ++wire) {
            const int g = layer * NQ + wire;
            const float2 u00 = Ufused[g][0], u01 = Ufused[g][1];
            const float2 u10 = Ufused[g][2], u11 = Ufused[g][3];
            const int b = 11 - wire;                 // flat-index bit for this wire
            const int lowmask = (1 << b) - 1;
            #pragma unroll
            for (int p = tid; p < NPAIRS; p += THREADS) {
                const int i0 = ((p & ~lowmask) << 1) | (p & lowmask);
                const int i1 = i0 | (1 << b);
                const float ar = re[i0], ai = im[i0];
                const float br = re[i1], bi = im[i1];
                re[i0] = u00.x * ar - u00.y * ai + u01.x * br - u01.y * bi;
                im[i0] = u00.x * ai + u00.y * ar + u01.x * bi + u01.y * br;
                re[i1] = u10.x * ar - u10.y * ai + u11.x * br - u11.y * bi;
                im[i1] = u10.x * ai + u10.y * ar + u11.x * bi + u11.y * br;
            }
            __syncthreads();
        }
        // 12 CRX ring gates
        for (int k = 0; k < NQ; ++k) {
            const int ctrl = (layer == 0) ? k : (11 - k);
            const int tgt  = (ctrl + 1) % NQ;
            const int g    = layer * NQ + k;         // tape-order slot -> angle slot
            const float uc = crx_c[g], us = crx_s[g];
            const int bt = 11 - tgt;
            const int bc = 11 - ctrl;
            const int lowmask = (1 << bt) - 1;
            #pragma unroll
            for (int p = tid; p < NPAIRS; p += THREADS) {
                const int i0 = ((p & ~lowmask) << 1) | (p & lowmask);
                if ((i0 >> bc) & 1) {
                    const int i1 = i0 | (1 << bt);
                    const float ar = re[i0], ai = im[i0];
                    const float br = re[i1], bi = im[i1];
                    // RX: new0 = c*a - i s * b ; new1 = -i s * a + c*b
                    re[i0] = uc * ar + us * bi;
                    im[i0] = uc * ai - us * br;
                    re[i1] = uc * br + us * ai;
                    im[i1] = uc * bi - us * ar;
                }
            }
            __syncthreads();
        }
    }

    // ---- Expectation values <X_q>, <Y_q>, <Z_q> ----
    for (int q = 0; q < NQ; ++q) {
        const int b = 11 - q;
        const int lowmask = (1 << b) - 1;
        float z = 0.0f, cr = 0.0f, ci = 0.0f;
        #pragma unroll
        for (int p = tid; p < NPAIRS; p += THREADS) {
            const int i0 = ((p & ~lowmask) << 1) | (p & lowmask);
            const int i1 = i0 | (1 << b);
            const float ar = re[i0], ai = im[i0];
            const float br = re[i1], bi = im[i1];
            z  += ar * ar + ai * ai - br * br - bi * bi;
            cr += ar * br + ai * bi;     // Re(conj(p0)*p1)
            ci += ar * bi - ai * br;     // Im(conj(p0)*p1)
        }
        #pragma unroll
        for (int o = 16; o > 0; o >>= 1) {
            z  += __shfl_xor_sync(0xffffffffu, z,  o);
            cr += __shfl_xor_sync(0xffffffffu, cr, o);
            ci += __shfl_xor_sync(0xffffffffu, ci, o);
        }
        if ((tid & 31) == 0) {
            atomicAdd(&feats[q],          2.0f * cr);  // X
            atomicAdd(&feats[NQ + q],     2.0f * ci);  // Y
            atomicAdd(&feats[2 * NQ + q], z);          // Z
        }
    }
    __syncthreads();

    // ---- Linear head: out = feats @ W^T + b ----
    if (tid < NCLASSES) {
        float acc = bv[tid];
        #pragma unroll
        for (int j = 0; j < NFEAT; ++j)
            acc += Wm[tid * NFEAT + j] * feats[j];
        out[(size_t)bidx * NCLASSES + tid] = acc;
    }
}

extern "C" void kernel_launch(void* const* d_in, const int* in_sizes, int n_in,
                              void* d_out, int out_size)
{
    const float* sv     = (const float*)d_in[0];  // [2048, 4096]
    const float* angles = (const float*)d_in[1];  // [96]
    const float* Wm     = (const float*)d_in[2];  // [10, 36]
    const float* bv     = (const float*)d_in[3];  // [10]
    float* out          = (float*)d_out;          // [2048, 10]
    (void)in_sizes; (void)n_in; (void)out_size;

    qsim_kernel<<<2048, THREADS>>>(sv, angles, Wm, bv, out);
}

// round 2
// speedup vs baseline: 2.2202x; 2.2202x over previous
#include <cuda_runtime.h>

#define NQ       12
#define DIM      4096
#define THREADS  256
#define NCLASSES 10
#define NFEAT    36

struct Cx { float x, y; };
struct Amp { float r, i; };

__device__ __forceinline__ Cx cmul(Cx a, Cx b) {
    return Cx{a.x * b.x - a.y * b.y, a.x * b.y + a.y * b.x};
}

// XOR swizzle: phys(i) = i ^ bits5..9(i) folded into bits0..4.
// Distributes over disjoint bit fields: swz(a|b) = swz(a)^swz(b) when a&b==0.
__device__ __forceinline__ int swzc(int i) { return i ^ ((i >> 5) & 31); }

template<int S0,int S1,int S2,int S3>
__device__ __forceinline__ int offj(int j) {
    return ((j & 1) << S0) | (((j >> 1) & 1) << S1) | (((j >> 2) & 1) << S2) | (((j >> 3) & 1) << S3);
}

template<int L0,int L1,int L2,int L3,int L4,int W0,int W1,int W2>
__device__ __forceinline__ int mkbase(int t) {
    return ((t & 1) << L0) | (((t >> 1) & 1) << L1) | (((t >> 2) & 1) << L2) |
           (((t >> 3) & 1) << L3) | (((t >> 4) & 1) << L4) |
           (((t >> 5) & 1) << W0) | (((t >> 6) & 1) << W1) | (((t >> 7) & 1) << W2);
}

template<int S0,int S1,int S2,int S3>
__device__ __forceinline__ void ld16(Amp a[16], const float* re, const float* im, int pb) {
#pragma unroll
    for (int j = 0; j < 16; j++) {
        const int ad = pb ^ swzc(offj<S0,S1,S2,S3>(j));
        a[j].r = re[ad]; a[j].i = im[ad];
    }
}

template<int S0,int S1,int S2,int S3>
__device__ __forceinline__ void st16(const Amp a[16], float* re, float* im, int pb) {
#pragma unroll
    for (int j = 0; j < 16; j++) {
        const int ad = pb ^ swzc(offj<S0,S1,S2,S3>(j));
        re[ad] = a[j].r; im[ad] = a[j].i;
    }
}

// Fused 1q gate on local bit K of the 16-amp register tile.
template<int K>
__device__ __forceinline__ void g1q(Amp a[16], const float2* U) {
    const float2 u00 = U[0], u01 = U[1], u10 = U[2], u11 = U[3];
#pragma unroll
    for (int j = 0; j < 16; j++) {
        if (((j >> K) & 1) == 0) {
            const int j1 = j | (1 << K);
            const float ar = a[j].r, ai = a[j].i, br = a[j1].r, bi = a[j1].i;
            a[j].r  = u00.x*ar - u00.y*ai + u01.x*br - u01.y*bi;
            a[j].i  = u00.x*ai + u00.y*ar + u01.x*bi + u01.y*br;
            a[j1].r = u10.x*ar - u10.y*ai + u11.x*br - u11.y*bi;
            a[j1].i = u10.x*ai + u10.y*ar + u11.x*bi + u11.y*br;
        }
    }
}

// CRX: control local bit KC, target local bit KT.
template<int KC,int KT>
__device__ __forceinline__ void gcrx(Amp a[16], float c, float s) {
#pragma unroll
    for (int j = 0; j < 16; j++) {
        if (((j >> KC) & 1) == 1 && ((j >> KT) & 1) == 0) {
            const int j1 = j | (1 << KT);
            const float ar = a[j].r, ai = a[j].i, br = a[j1].r, bi = a[j1].i;
            a[j].r  = c*ar + s*bi;
            a[j].i  = c*ai - s*br;
            a[j1].r = c*br + s*ai;
            a[j1].i = c*bi - s*ar;
        }
    }
}

__device__ __forceinline__ void red_add(float v, float* dst) {
#pragma unroll
    for (int o = 16; o > 0; o >>= 1) v += __shfl_xor_sync(0xffffffffu, v, o);
    if ((threadIdx.x & 31) == 0) atomicAdd(dst, v);
}

// <X>,<Y> across local bit K; qubit index q.
template<int K>
__device__ __forceinline__ void cross_xy(const Amp a[16], float* feats, int q) {
    float cr = 0.f, ci = 0.f;
#pragma unroll
    for (int j = 0; j < 16; j++) {
        if (((j >> K) & 1) == 0) {
            const int j1 = j | (1 << K);
            cr += a[j].r*a[j1].r + a[j].i*a[j1].i;
            ci += a[j].r*a[j1].i - a[j].i*a[j1].r;
        }
    }
    red_add(2.f * cr, &feats[q]);
    red_add(2.f * ci, &feats[NQ + q]);
}

__global__ __launch_bounds__(THREADS)
void qsim_kernel(const float* __restrict__ sv,
                 const float* __restrict__ angles,
                 const float* __restrict__ Wm,
                 const float* __restrict__ bv,
                 float* __restrict__ out)
{
    __shared__ float re[DIM];
    __shared__ float im[DIM];
    __shared__ float2 U[24][4];        // fused RZ*RY*RX, [layer*12+wire]
    __shared__ float cc[24], cs[24];   // CRX cos/sin, tape-slot order
    __shared__ float feats[NFEAT];

    const int tid  = threadIdx.x;
    const int bidx = blockIdx.x;

    if (tid < 24) {
        const int layer = tid / NQ;
        const int wire  = tid % NQ;
        const int base  = layer * 48;
        const float tx = angles[base + wire];
        const float ty = angles[base + 12 + wire];
        const float tz = angles[base + 24 + wire];
        const float cxv = cosf(0.5f*tx), sxv = sinf(0.5f*tx);
        const float cyv = cosf(0.5f*ty), syv = sinf(0.5f*ty);
        const float czv = cosf(0.5f*tz), szv = sinf(0.5f*tz);
        Cx m00{cyv*cxv,  syv*sxv};
        Cx m01{-syv*cxv, -cyv*sxv};
        Cx m10{syv*cxv,  -cyv*sxv};
        Cx m11{cyv*cxv,  -syv*sxv};
        Cx ezm{czv, -szv}, ezp{czv, szv};
        Cx u00 = cmul(ezm, m00), u01 = cmul(ezm, m01);
        Cx u10 = cmul(ezp, m10), u11 = cmul(ezp, m11);
        U[tid][0] = make_float2(u00.x, u00.y);
        U[tid][1] = make_float2(u01.x, u01.y);
        U[tid][2] = make_float2(u10.x, u10.y);
        U[tid][3] = make_float2(u11.x, u11.y);
        const float tc = angles[base + 36 + wire];
        cc[tid] = cosf(0.5f*tc);
        cs[tid] = sinf(0.5f*tc);
    }
    if (tid < NFEAT) feats[tid] = 0.0f;
    __syncthreads();

    Amp a[16];

    // ---- Pass 1: S={8,9,10,11}  (load gmem; L0 1q wires 0-3; CRX slots 0,1,2) ----
    {
        const float* in = sv + (size_t)bidx * DIM;
#pragma unroll
        for (int j = 0; j < 16; j++) { a[j].r = in[(j << 8) | tid]; a[j].i = 0.f; }
        g1q<0>(a, U[3]);  // bit8  = wire3
        g1q<1>(a, U[2]);
        g1q<2>(a, U[1]);
        g1q<3>(a, U[0]);
        gcrx<3,2>(a, cc[0], cs[0]);   // CRX(0,1): bits(11,10)
        gcrx<2,1>(a, cc[1], cs[1]);   // CRX(1,2): bits(10,9)
        gcrx<1,0>(a, cc[2], cs[2]);   // CRX(2,3): bits(9,8)
        st16<8,9,10,11>(a, re, im, swzc(tid));
    }
    __syncthreads();

    // ---- Pass 2: S={5,6,7,8}  (L0 1q wires 6,5,4; CRX slots 3,4,5) ----
    {
        const int pb = swzc(mkbase<0,1,2,3,4, 9,10,11>(tid));
        ld16<5,6,7,8>(a, re, im, pb);
        g1q<0>(a, U[6]);  // bit5 = wire6
        g1q<1>(a, U[5]);
        g1q<2>(a, U[4]);
        gcrx<3,2>(a, cc[3], cs[3]);   // CRX(3,4): bits(8,7)
        gcrx<2,1>(a, cc[4], cs[4]);   // CRX(4,5): bits(7,6)
        gcrx<1,0>(a, cc[5], cs[5]);   // CRX(5,6): bits(6,5)
        st16<5,6,7,8>(a, re, im, pb);
    }
    __syncthreads();

    // ---- Pass 3: S={2,3,4,5}  (L0 1q wires 9,8,7; CRX slots 6,7,8) ----
    {
        const int pb = swzc(mkbase<0,1,7,8,9, 6,10,11>(tid));
        ld16<2,3,4,5>(a, re, im, pb);
        g1q<0>(a, U[9]);  // bit2 = wire9
        g1q<1>(a, U[8]);
        g1q<2>(a, U[7]);
        gcrx<3,2>(a, cc[6], cs[6]);   // CRX(6,7): bits(5,4)
        gcrx<2,1>(a, cc[7], cs[7]);   // CRX(7,8): bits(4,3)
        gcrx<1,0>(a, cc[8], cs[8]);   // CRX(8,9): bits(3,2)
        st16<2,3,4,5>(a, re, im, pb);
    }
    __syncthreads();

    // ---- Pass 4 (mega): S={0,1,2,11}
    //   L0 1q wires 11,10; CRX slots 9,10,11; L1 1q wires 11,10,9,0; L1 CRX slots 12,13,14 ----
    {
        const int pb = swzc(mkbase<3,4,5,6,7, 8,9,10>(tid));
        ld16<0,1,2,11>(a, re, im, pb);
        g1q<0>(a, U[11]);             // bit0 = wire11 (L0)
        g1q<1>(a, U[10]);             // bit1 = wire10 (L0)
        gcrx<2,1>(a, cc[9],  cs[9]);  // CRX(9,10):  bits(2,1)
        gcrx<1,0>(a, cc[10], cs[10]); // CRX(10,11): bits(1,0)
        gcrx<0,3>(a, cc[11], cs[11]); // CRX(11,0):  ctrl bit0, tgt bit11
        g1q<0>(a, U[23]);             // bit0  = wire11 (L1)
        g1q<1>(a, U[22]);             // bit1  = wire10 (L1)
        g1q<2>(a, U[21]);             // bit2  = wire9  (L1)
        g1q<3>(a, U[12]);             // bit11 = wire0  (L1)
        gcrx<0,3>(a, cc[12], cs[12]); // L1 CRX(11,0):  bits(0,11)
        gcrx<1,0>(a, cc[13], cs[13]); // L1 CRX(10,11): bits(1,0)
        gcrx<2,1>(a, cc[14], cs[14]); // L1 CRX(9,10):  bits(2,1)
        st16<0,1,2,11>(a, re, im, pb);
    }
    __syncthreads();

    // ---- Pass 5: S={2,3,4,5}  (L1 1q wires 8,7,6; CRX slots 15,16,17) ----
    {
        const int pb = swzc(mkbase<0,1,7,8,9, 6,10,11>(tid));
        ld16<2,3,4,5>(a, re, im, pb);
        g1q<1>(a, U[20]);  // bit3 = wire8 (L1)
        g1q<2>(a, U[19]);
        g1q<3>(a, U[18]);
        gcrx<1,0>(a, cc[15], cs[15]); // CRX(8,9): bits(3,2)
        gcrx<2,1>(a, cc[16], cs[16]); // CRX(7,8): bits(4,3)
        gcrx<3,2>(a, cc[17], cs[17]); // CRX(6,7): bits(5,4)
        st16<2,3,4,5>(a, re, im, pb);
    }
    __syncthreads();

    // ---- Pass 6: S={5,6,7,8}  (L1 1q wires 5,4,3; CRX slots 18,19,20) ----
    {
        const int pb = swzc(mkbase<0,1,2,3,4, 9,10,11>(tid));
        ld16<5,6,7,8>(a, re, im, pb);
        g1q<1>(a, U[17]);  // bit6 = wire5 (L1)
        g1q<2>(a, U[16]);
        g1q<3>(a, U[15]);
        gcrx<1,0>(a, cc[18], cs[18]); // CRX(5,6): bits(6,5)
        gcrx<2,1>(a, cc[19], cs[19]); // CRX(4,5): bits(7,6)
        gcrx<3,2>(a, cc[20], cs[20]); // CRX(3,4): bits(8,7)
        st16<5,6,7,8>(a, re, im, pb);
    }
    __syncthreads();

    // ---- Pass 7: S={8,9,10,11}  (L1 1q wires 2,1; CRX slots 21,22,23; + expvals) ----
    {
        const int pb = swzc(tid);
        ld16<8,9,10,11>(a, re, im, pb);
        g1q<1>(a, U[14]);  // bit9  = wire2 (L1)
        g1q<2>(a, U[13]);  // bit10 = wire1 (L1)
        gcrx<1,0>(a, cc[21], cs[21]); // CRX(2,3): bits(9,8)
        gcrx<2,1>(a, cc[22], cs[22]); // CRX(1,2): bits(10,9)
        gcrx<3,2>(a, cc[23], cs[23]); // CRX(0,1): bits(11,10)
        st16<8,9,10,11>(a, re, im, pb);

        // Expvals: all <Z>, plus <X>,<Y> for qubits 0-3 (bits 11-8)
        float tot = 0.f, d0 = 0.f, d1 = 0.f, d2 = 0.f, d3 = 0.f;
#pragma unroll
        for (int j = 0; j < 16; j++) {
            const float p = a[j].r*a[j].r + a[j].i*a[j].i;
            tot += p;
            if (j & 1) d0 += p;
            if (j & 2) d1 += p;
            if (j & 4) d2 += p;
            if (j & 8) d3 += p;
        }
        red_add(tot - 2.f*d0, &feats[24 + 3]);  // bit8  -> qubit3
        red_add(tot - 2.f*d1, &feats[24 + 2]);
        red_add(tot - 2.f*d2, &feats[24 + 1]);
        red_add(tot - 2.f*d3, &feats[24 + 0]);
#pragma unroll
        for (int b = 0; b < 8; b++) {
            const float zv = ((tid >> b) & 1) ? -tot : tot;
            red_add(zv, &feats[24 + (11 - b)]);  // free bit b -> qubit 11-b
        }
        cross_xy<0>(a, feats, 3);
        cross_xy<1>(a, feats, 2);
        cross_xy<2>(a, feats, 1);
        cross_xy<3>(a, feats, 0);
    }
    __syncthreads();

    // ---- Pass 8: expvals <X>,<Y> for qubits 7,6,5,4 (bits 4,5,6,7) ----
    {
        const int pb = swzc(mkbase<0,1,2,3,9, 8,10,11>(tid));
        ld16<4,5,6,7>(a, re, im, pb);
        cross_xy<0>(a, feats, 7);
        cross_xy<1>(a, feats, 6);
        cross_xy<2>(a, feats, 5);
        cross_xy<3>(a, feats, 4);
    }

    // ---- Pass 9: expvals <X>,<Y> for qubits 11,10,9,8 (bits 0,1,2,3) ----
    {
        const int pb = swzc(mkbase<4,5,6,7,8, 9,10,11>(tid));
        ld16<0,1,2,3>(a, re, im, pb);
        cross_xy<0>(a, feats, 11);
        cross_xy<1>(a, feats, 10);
        cross_xy<2>(a, feats, 9);
        cross_xy<3>(a, feats, 8);
    }
    __syncthreads();

    // ---- Linear head ----
    if (tid < NCLASSES) {
        float acc = bv[tid];
#pragma unroll
        for (int j = 0; j < NFEAT; ++j)
            acc += Wm[tid * NFEAT + j] * feats[j];
        out[(size_t)bidx * NCLASSES + tid] = acc;
    }
}

extern "C" void kernel_launch(void* const* d_in, const int* in_sizes, int n_in,
                              void* d_out, int out_size)
{
    const float* sv     = (const float*)d_in[0];  // [2048, 4096]
    const float* angles = (const float*)d_in[1];  // [96]
    const float* Wm     = (const float*)d_in[2];  // [10, 36]
    const float* bv     = (const float*)d_in[3];  // [10]
    float* out          = (float*)d_out;          // [2048, 10]
    (void)in_sizes; (void)n_in; (void)out_size;

    qsim_kernel<<<2048, THREADS>>>(sv, angles, Wm, bv, out);
}